// round 17
// baseline (speedup 1.0000x reference)
#include <cuda_runtime.h>

// PerturbedTopK: x (64,196) f32, noise (64,500,196) f32.
// out[b,k,d] = mean_n [ sorted(top49_idx(x_b + 0.05*noise_bn))[k] == d ].
//
// R17: long-lived warps. grid (25,64) x 128: each warp owns 5 rows
// (rib = blockIdx.x*4+wid + 100*i), so warps desynchronize after row 1 and
// stalls overlap across warps (the 1-row/warp variants stalled in lockstep).
// Per-block seed: warp 0 finds batch threshold T_b from x, one syncthreads.
// Row body (proven R15): float4 loads, key-domain boundary-jump select
// (+-1 bookkeeping, single verify, skip when seed count exact), parallel
// 8-ballot emit with exact ascending-index two-sided ranks, direct REDG
// atomicAdd(1/500) into memset-zeroed out. Ties/cap -> exact MSB radix
// fallback (same layout, index-order tie-break).
//
// Layout: lane L, slot s=c*4+m -> d = c*128 + 4L + m (c in {0,1});
// chunk 1 valid only for L <= 16. All chunk-0 d < all chunk-1 d.

#define BATCH 64
#define NSAMP 500
#define DIM   196
#define TOPK  49
#define SIGMA 0.05f

#define OUTN  (BATCH * TOPK * DIM)
#define FULLM 0xffffffffu
#define NEGBIG (-3.402823466e38f)

__device__ __forceinline__ unsigned f2key(float v) {
    unsigned u = __float_as_uint(v);
    return u ^ ((unsigned)((int)u >> 31) | 0x80000000u);
}
__device__ __forceinline__ float key2f(unsigned k) {
    unsigned u = (k & 0x80000000u) ? (k ^ 0x80000000u) : ~k;
    return __uint_as_float(u);
}
__device__ __forceinline__ unsigned fgt(float a, float b) {
    unsigned r;
    asm("set.gt.u32.f32 %0, %1, %2;" : "=r"(r) : "f"(a), "f"(b));
    return r;
}
__device__ __forceinline__ unsigned ugt(unsigned a, unsigned b) {
    unsigned r;
    asm("set.gt.u32.u32 %0, %1, %2;" : "=r"(r) : "r"(a), "r"(b));
    return r;
}

__global__ __launch_bounds__(128)
void ptopk_kernel(const float* __restrict__ x,
                  const float* __restrict__ noise,
                  float* __restrict__ out) {
    __shared__ unsigned sKseed;

    const int wid  = threadIdx.x >> 5;
    const int lane = threadIdx.x & 31;
    const int b    = blockIdx.y;

    const unsigned lt  = (1u << lane) - 1u;
    const unsigned lte = lt | (1u << lane);
    const bool hasC1 = (lane <= 16);
    const float invn = 1.0f / (float)NSAMP;
    float* __restrict__ outb = out + (size_t)b * (TOPK * DIM);

    // x row as float4 (held for the whole warp lifetime).
    const float4* x4 = reinterpret_cast<const float4*>(x + b * DIM);
    const float4 xa0 = x4[lane];
    const float4 xa1 = hasC1 ? x4[32 + lane]
                             : make_float4(NEGBIG, NEGBIG, NEGBIG, NEGBIG);

    // Warp 0: batch seed threshold from x (hint only; any value is safe).
    if (wid == 0) {
        float xv[8] = { xa0.x, xa0.y, xa0.z, xa0.w, xa1.x, xa1.y, xa1.z, xa1.w };
        float piv = 0.674f;
        #pragma unroll 1
        for (int it = 0; it < 24; ++it) {
            unsigned a = 0;
            #pragma unroll
            for (int s = 0; s < 8; s++) a += fgt(xv[s], piv);
            const int c = -(int)__reduce_add_sync(FULLM, (int)a);
            if (c == TOPK) break;
            const int dd = c - TOPK;
            if (dd > 3 || dd < -3) {
                piv = fmaf((float)dd, 0.0161f, piv);         // Newton
            } else if (dd > 0) {
                unsigned mk = 0xFFFFFFFFu;
                #pragma unroll
                for (int s = 0; s < 8; s++)
                    mk = min(mk, (xv[s] > piv) ? f2key(xv[s]) : 0xFFFFFFFFu);
                piv = key2f(__reduce_min_sync(FULLM, mk));
            } else {
                unsigned Mk = 0u;
                #pragma unroll
                for (int s = 0; s < 8; s++)
                    Mk = max(Mk, (xv[s] > piv) ? 0u : f2key(xv[s]));
                piv = key2f(__reduce_max_sync(FULLM, Mk) - 1u);
            }
        }
        if (lane == 0) sKseed = f2key(piv);
    }
    __syncthreads();
    const unsigned Kseed = sKseed;

    const float* __restrict__ nbase = noise + (size_t)b * NSAMP * DIM;

    #pragma unroll 1
    for (int i = 0; i < 5; i++) {
        const int rib = blockIdx.x * 4 + wid + 100 * i;      // [0,500)
        const float4* n4 = reinterpret_cast<const float4*>(nbase + (size_t)rib * DIM);

        const float4 nx0 = n4[lane];
        const float4 nx1 = hasC1 ? n4[32 + lane] : make_float4(0, 0, 0, 0);

        // Keys: slot s=c*4+m -> d=c*128+4*lane+m. Padding -> key 0.
        unsigned key[8];
        key[0] = f2key(fmaf(nx0.x, SIGMA, xa0.x));
        key[1] = f2key(fmaf(nx0.y, SIGMA, xa0.y));
        key[2] = f2key(fmaf(nx0.z, SIGMA, xa0.z));
        key[3] = f2key(fmaf(nx0.w, SIGMA, xa0.w));
        key[4] = hasC1 ? f2key(fmaf(nx1.x, SIGMA, xa1.x)) : 0u;
        key[5] = hasC1 ? f2key(fmaf(nx1.y, SIGMA, xa1.y)) : 0u;
        key[6] = hasC1 ? f2key(fmaf(nx1.z, SIGMA, xa1.z)) : 0u;
        key[7] = hasC1 ? f2key(fmaf(nx1.w, SIGMA, xa1.w)) : 0u;

        // Count at the batch-seeded threshold.
        unsigned Kthr = Kseed;
        unsigned a = 0;
        #pragma unroll
        for (int s = 0; s < 8; s++) a += ugt(key[s], Kthr);  // -1 per hit
        int c = -(int)__reduce_add_sync(FULLM, (int)a);

        // Boundary jumps: +-1 bookkeeping; verify only if we jumped.
        int cv = c;
        if (c != TOPK) {
            #pragma unroll 1
            for (int it = 0; it < 12 && c != TOPK; ++it) {
                if (c > TOPK) {
                    unsigned mk = 0xFFFFFFFFu;               // min selected
                    #pragma unroll
                    for (int s = 0; s < 8; s++)
                        mk = min(mk, (key[s] > Kthr) ? key[s] : 0xFFFFFFFFu);
                    Kthr = __reduce_min_sync(FULLM, mk);
                    c -= 1;
                } else {
                    unsigned Mk = 0u;                        // max unselected
                    #pragma unroll
                    for (int s = 0; s < 8; s++)
                        Mk = max(Mk, (key[s] > Kthr) ? 0u : key[s]);
                    Kthr = __reduce_max_sync(FULLM, Mk) - 1u;
                    c += 1;
                }
            }
            unsigned a2 = 0;
            #pragma unroll
            for (int s = 0; s < 8; s++) a2 += ugt(key[s], Kthr);
            cv = -(int)__reduce_add_sync(FULLM, (int)a2);
        }

        if (cv == TOPK) {
            // Parallel-ballot emit: exact ascending-d ranks.
            unsigned bb[8];
            #pragma unroll
            for (int s = 0; s < 8; s++)
                bb[s] = __ballot_sync(FULLM, key[s] > Kthr);
            const int t0 = __popc(bb[0]) + __popc(bb[1]) + __popc(bb[2]) + __popc(bb[3]);
            #pragma unroll
            for (int cch = 0; cch < 2; cch++) {
                #pragma unroll
                for (int m = 0; m < 4; m++) {
                    const int s = cch * 4 + m;
                    if (key[s] > Kthr) {
                        int rank = cch ? t0 : 0;
                        #pragma unroll
                        for (int mp = 0; mp < 4; mp++)
                            rank += __popc(bb[cch * 4 + mp] & (mp < m ? lte : lt));
                        const int d = cch * 128 + 4 * lane + m;
                        atomicAdd(outb + rank * DIM + d, invn);
                    }
                }
            }
        } else {
            // Exact MSB radix fallback, index-order tie-break (cold).
            unsigned actm = hasC1 ? 0xFFu : 0x0Fu;
            int k = TOPK, matching = DIM, sh = 0;
            unsigned P = 0u;
            #pragma unroll 1
            for (int bit = 31; bit >= 0; --bit) {
                const unsigned m = 1u << bit;
                int cc = 0;
                #pragma unroll
                for (int s = 0; s < 8; s++)
                    cc += (((actm >> s) & 1u) && (key[s] & m)) ? 1 : 0;
                cc = __reduce_add_sync(FULLM, cc);
                if (cc >= k) {
                    P |= m; matching = cc;
                    #pragma unroll
                    for (int s = 0; s < 8; s++)
                        if (!(key[s] & m)) actm &= ~(1u << s);
                } else {
                    k -= cc; matching -= cc;
                    #pragma unroll
                    for (int s = 0; s < 8; s++)
                        if (key[s] & m) actm &= ~(1u << s);
                }
                sh = bit;
                if (matching == k) break;
            }
            const unsigned Ph = P >> sh;
            unsigned gb[8], eb[8];
            #pragma unroll
            for (int s = 0; s < 8; s++) {
                const bool valid = (s < 4) || hasC1;
                gb[s] = __ballot_sync(FULLM, valid && ((key[s] >> sh) > Ph));
                eb[s] = __ballot_sync(FULLM, ((actm >> s) & 1u) != 0u);
            }
            const int g0 = __popc(gb[0]) + __popc(gb[1]) + __popc(gb[2]) + __popc(gb[3]);
            const int e0 = __popc(eb[0]) + __popc(eb[1]) + __popc(eb[2]) + __popc(eb[3]);
            #pragma unroll
            for (int cch = 0; cch < 2; cch++) {
                #pragma unroll
                for (int m = 0; m < 4; m++) {
                    const int s = cch * 4 + m;
                    const bool valid = (s < 4) || hasC1;
                    const bool gt = valid && ((key[s] >> sh) > Ph);
                    const bool eq = ((actm >> s) & 1u) != 0u;
                    if (gt || eq) {
                        int gtp = cch ? g0 : 0, eqp = cch ? e0 : 0;
                        #pragma unroll
                        for (int mp = 0; mp < 4; mp++) {
                            gtp += __popc(gb[cch * 4 + mp] & (mp < m ? lte : lt));
                            eqp += __popc(eb[cch * 4 + mp] & (mp < m ? lte : lt));
                        }
                        if (gt || (eq && eqp < k)) {
                            const int rank = gtp + min(eqp, k);
                            const int d = cch * 128 + 4 * lane + m;
                            atomicAdd(outb + rank * DIM + d, invn);
                        }
                    }
                }
            }
        }
    }
}

extern "C" void kernel_launch(void* const* d_in, const int* in_sizes, int n_in,
                              void* d_out, int out_size) {
    const float* x     = (const float*)d_in[0];
    const float* noise = (const float*)d_in[1];
    if (n_in >= 2 && in_sizes[0] > in_sizes[1]) {
        x     = (const float*)d_in[1];
        noise = (const float*)d_in[0];
    }
    float* out = (float*)d_out;

    cudaMemsetAsync(out, 0, (size_t)OUTN * sizeof(float));
    dim3 grid(25, BATCH, 1);    // 25 blocks x 4 warps x 5 rows = 500 rows/batch
    ptopk_kernel<<<grid, 128>>>(x, noise, out);
}